// round 16
// baseline (speedup 1.0000x reference)
#include <cuda_runtime.h>
#include <cuda_fp16.h>
#include <cstdint>

#define N_PAD   50048
#define DIM     256
#define NEG     0.2f
#define LN_EPS  1e-5f
#define THREADS 512
#define NCTA    148

// SMEM layout (bytes): B 4 chunk-planes | A16 4 planes | Vs  (identical to R13)
#define B_CHUNK  32768
#define A16_OFF  131072
#define VS_OFF   163840
#define VS       264
#define SMEM_BYTES (VS_OFF + 64 * VS * 4)   // 231424

// ---------------- scratch ----------------
__device__ unsigned char g_mask[3 * N_PAD];
__device__ int g_cnt;     // zero-init; sense-reversing grid barrier
__device__ int g_phase;

// ---------------- helpers ----------------
__device__ __forceinline__ uint32_t pack_f16(float a, float b) {
    __half2 h = __floats2half2_rn(a, b);
    return *reinterpret_cast<uint32_t*>(&h);
}
__device__ __forceinline__ uint32_t s2u(const void* p) {
    return (uint32_t)__cvta_generic_to_shared(p);
}
__device__ __forceinline__ uint32_t swz(uint32_t off) {
    return off ^ ((off >> 3) & 0x70);
}
__device__ __forceinline__ void ldmx4(uint32_t r[4], uint32_t addr) {
    asm volatile("ldmatrix.sync.aligned.m8n8.x4.shared.b16 {%0,%1,%2,%3}, [%4];"
                 : "=r"(r[0]), "=r"(r[1]), "=r"(r[2]), "=r"(r[3]) : "r"(addr));
}
__device__ __forceinline__ void mma16816(float c[4], const uint32_t a[4],
                                         uint32_t b0, uint32_t b1) {
    asm("mma.sync.aligned.m16n8k16.row.col.f32.f16.f16.f32 "
        "{%0,%1,%2,%3}, {%4,%5,%6,%7}, {%8,%9}, {%0,%1,%2,%3};"
        : "+f"(c[0]), "+f"(c[1]), "+f"(c[2]), "+f"(c[3])
        : "r"(a[0]), "r"(a[1]), "r"(a[2]), "r"(a[3]), "r"(b0), "r"(b1));
}
__device__ __forceinline__ float head_w(float q, float kv, float n1) {
    float x1 = q + kv;
    float z1 = fmaxf(x1, NEG * x1);
    float z0 = fmaxf(q,  NEG * q);
    float m  = fmaxf(z1, z0);
    float e1 = expf(z1 - m);
    float e0 = expf(z0 - m);
    float f1 = n1 * e1;
    return f1 / (f1 + (4.0f - n1) * e0);
}

// ---------------- single fused persistent kernel ----------------
// 512 threads = 16 warps, warp grid 2m x 8n, warp tile 32x32 (validated R12/R13).
__global__ __launch_bounds__(THREADS, 1)
void fused_kernel(const float* __restrict__ feat,
                  const float* __restrict__ Wr,
                  const float* __restrict__ br,
                  const float* __restrict__ rel_q,
                  const float* __restrict__ rel_k,
                  const float* __restrict__ ln_g,
                  const float* __restrict__ ln_b,
                  const int* __restrict__ d0,
                  const int* __restrict__ d1,
                  const int* __restrict__ d2,
                  float* __restrict__ out, int n, int E4)
{
    extern __shared__ char smem[];
    const uint32_t su = s2u(smem);
    const int tid  = threadIdx.x;
    const int wid  = tid >> 5;
    const int lane = tid & 31;
    const int wm   = wid & 1;
    const int wn   = wid >> 1;

    // ===== prologue: edge scatter (cooperative slice) =====
    {
        int base = blockIdx.x * ((E4 + NCTA - 1) / NCTA);
        int end  = base + ((E4 + NCTA - 1) / NCTA);
        if (end > E4) end = E4;
        for (int i = base + tid; i < end; i += THREADS) {
            int4 a  = ((const int4*)d0)[i];
            int4 bb = ((const int4*)d1)[i];
            int4 cc = ((const int4*)d2)[i];
            if (!g_mask[a.x]) g_mask[a.x] = 1;
            if (!g_mask[a.y]) g_mask[a.y] = 1;
            if (!g_mask[a.z]) g_mask[a.z] = 1;
            if (!g_mask[a.w]) g_mask[a.w] = 1;
            if (!g_mask[N_PAD + bb.x]) g_mask[N_PAD + bb.x] = 1;
            if (!g_mask[N_PAD + bb.y]) g_mask[N_PAD + bb.y] = 1;
            if (!g_mask[N_PAD + bb.z]) g_mask[N_PAD + bb.z] = 1;
            if (!g_mask[N_PAD + bb.w]) g_mask[N_PAD + bb.w] = 1;
            if (!g_mask[2 * N_PAD + cc.x]) g_mask[2 * N_PAD + cc.x] = 1;
            if (!g_mask[2 * N_PAD + cc.y]) g_mask[2 * N_PAD + cc.y] = 1;
            if (!g_mask[2 * N_PAD + cc.z]) g_mask[2 * N_PAD + cc.z] = 1;
            if (!g_mask[2 * N_PAD + cc.w]) g_mask[2 * N_PAD + cc.w] = 1;
        }
        __threadfence();
    }

    // ===== prologue: Wr -> fp16 into smem B (L2-hot; per-CTA) =====
    // task t: nc = t&255 (coalesced across warp), seg = t>>8 (16 k's)
    {
        #pragma unroll
        for (int it = 0; it < 8; it++) {
            int t   = tid + it * THREADS;      // 0..4095
            int nc  = t & 255;
            int seg = t >> 8;
            int kb  = seg * 16;
            float x[16];
            #pragma unroll
            for (int q = 0; q < 16; q++) x[q] = Wr[(size_t)(kb + q) * 256 + nc];
            uint32_t h[8];
            #pragma unroll
            for (int p = 0; p < 8; p++) h[p] = pack_f16(x[2 * p], x[2 * p + 1]);
            char* plane = smem + (seg >> 2) * B_CHUNK;
            uint32_t base = (uint32_t)(nc * 128 + (seg & 3) * 32);
            *(uint4*)(plane + swz(base))      = make_uint4(h[0], h[1], h[2], h[3]);
            *(uint4*)(plane + swz(base + 16)) = make_uint4(h[4], h[5], h[6], h[7]);
        }
    }

    // fragment address components (validated R12/R13)
    const int l7  = lane & 7;
    const int q01 = (lane >> 3) & 1;
    const int q23 = lane >> 4;
    uint32_t arowb[2];
    #pragma unroll
    for (int mt = 0; mt < 2; mt++)
        arowb[mt] = (uint32_t)((wm * 32 + mt * 16 + q01 * 8 + l7) * 128);
    const uint32_t bg   = (uint32_t)((lane >> 3) * 16);
    const uint32_t brb0 = (uint32_t)((wn * 32 + l7) * 128);

    // A staging mapping (validated R13)
    const int arow = tid >> 3;
    const int aseg = tid & 7;
    char* aplane = smem + A16_OFF + (aseg >> 1) * 8192;
    const uint32_t abase = (uint32_t)(arow * 128 + (aseg & 1) * 64);

    float* Vs = (float*)(smem + VS_OFF);
    const int ntiles = (n + 63) >> 6;
    const int stride = gridDim.x;

    // ===== prologue: A(first tile) load + convert =====
    {
        int gr = blockIdx.x * 64 + arow; if (gr >= n) gr = n - 1;
        const float4* af = (const float4*)(feat + (size_t)gr * 256 + aseg * 32);
        float4 v[8];
        #pragma unroll
        for (int i = 0; i < 8; i++) v[i] = af[i];
        #pragma unroll
        for (int j = 0; j < 4; j++) {
            uint4 h = make_uint4(pack_f16(v[2*j].x,   v[2*j].y),
                                 pack_f16(v[2*j].z,   v[2*j].w),
                                 pack_f16(v[2*j+1].x, v[2*j+1].y),
                                 pack_f16(v[2*j+1].z, v[2*j+1].w));
            *(uint4*)(aplane + swz(abase + j * 16)) = h;
        }
    }

    // ===== grid barrier (all 148 CTAs resident -> deadlock-free) =====
    __syncthreads();   // all scatter stores + fences done CTA-wide
    if (tid == 0) {
        int ph = *(volatile int*)&g_phase;
        if (atomicAdd(&g_cnt, 1) == (int)gridDim.x - 1) {
            g_cnt = 0;
            __threadfence();
            atomicAdd(&g_phase, 1);
        } else {
            while (*(volatile int*)&g_phase == ph) { }
        }
    }

    for (int s = blockIdx.x; s < ntiles; s += stride) {
        const int row0 = s * 64;
        __syncthreads();   // B1: A16(s) + B ready

        float acc[2][4][4];
        #pragma unroll
        for (int mt = 0; mt < 2; mt++)
            #pragma unroll
            for (int nt = 0; nt < 4; nt++)
                #pragma unroll
                for (int q = 0; q < 4; q++) acc[mt][nt][q] = 0.0f;

        // ---- compute: 8 steps (c,p), fragment double-buffered ----
        uint32_t bhf[2][4][4], ahf[2][2][2][4];
        // load step 0
        {
            const uint32_t sa = su + A16_OFF;
            const uint32_t sb = su;
            #pragma unroll
            for (int nt = 0; nt < 4; nt++)
                ldmx4(bhf[0][nt], sb + swz(brb0 + (uint32_t)(nt * 1024) + bg));
            #pragma unroll
            for (int mt = 0; mt < 2; mt++)
                #pragma unroll
                for (int kk = 0; kk < 2; kk++)
                    ldmx4(ahf[0][mt][kk], sa + swz(arowb[mt] + (uint32_t)(kk * 32 + q23 * 16)));
        }
        #pragma unroll
        for (int step = 0; step < 8; step++) {
            const int b  = step & 1;
            const int nb = b ^ 1;
            if (step < 7) {   // prefetch step+1 fragments
                const int c2 = (step + 1) >> 1;
                const int p2 = (step + 1) & 1;
                const uint32_t sa = su + A16_OFF + (uint32_t)c2 * 8192;
                const uint32_t sb = su + (uint32_t)c2 * B_CHUNK;
                #pragma unroll
                for (int nt = 0; nt < 4; nt++)
                    ldmx4(bhf[nb][nt], sb + swz(brb0 + (uint32_t)(nt * 1024 + p2 * 64) + bg));
                #pragma unroll
                for (int mt = 0; mt < 2; mt++)
                    #pragma unroll
                    for (int kk = 0; kk < 2; kk++)
                        ldmx4(ahf[nb][mt][kk], sa + swz(arowb[mt] + (uint32_t)((p2 * 2 + kk) * 32 + q23 * 16)));
            }
            #pragma unroll
            for (int kk = 0; kk < 2; kk++) {
                mma16816(acc[0][0], ahf[b][0][kk], bhf[b][0][2*kk], bhf[b][0][2*kk+1]);
                mma16816(acc[1][0], ahf[b][1][kk], bhf[b][0][2*kk], bhf[b][0][2*kk+1]);
                mma16816(acc[0][1], ahf[b][0][kk], bhf[b][1][2*kk], bhf[b][1][2*kk+1]);
                mma16816(acc[1][1], ahf[b][1][kk], bhf[b][1][2*kk], bhf[b][1][2*kk+1]);
                mma16816(acc[0][2], ahf[b][0][kk], bhf[b][2][2*kk], bhf[b][2][2*kk+1]);
                mma16816(acc[1][2], ahf[b][1][kk], bhf[b][2][2*kk], bhf[b][2][2*kk+1]);
                mma16816(acc[0][3], ahf[b][0][kk], bhf[b][3][2*kk], bhf[b][3][2*kk+1]);
                mma16816(acc[1][3], ahf[b][1][kk], bhf[b][3][2*kk], bhf[b][3][2*kk+1]);
            }
        }

        // ---- prefetch A(s+stride): issue LDGs now, consume after epilogue ----
        const int snext = s + stride;
        float4 vA[8];
        if (snext < ntiles) {
            int gr = snext * 64 + arow; if (gr >= n) gr = n - 1;
            const float4* af = (const float4*)(feat + (size_t)gr * 256 + aseg * 32);
            #pragma unroll
            for (int i = 0; i < 8; i++) vA[i] = af[i];
        }

        // ---- stage v tile to Vs (validated R13) ----
        {
            const int rg = lane >> 2;
            const int cq = (lane & 3) * 2;
            #pragma unroll
            for (int mt = 0; mt < 2; mt++)
                #pragma unroll
                for (int nt = 0; nt < 4; nt++) {
                    int r  = wm * 32 + mt * 16 + rg;
                    int cc = wn * 32 + nt * 8 + cq;
                    Vs[r * VS + cc]           = acc[mt][nt][0];
                    Vs[r * VS + cc + 1]       = acc[mt][nt][1];
                    Vs[(r + 8) * VS + cc]     = acc[mt][nt][2];
                    Vs[(r + 8) * VS + cc + 1] = acc[mt][nt][3];
                }
        }
        __syncthreads();   // B2: Vs complete, compute done

        // ---- epilogue (validated R13): 16 warps x 4 rows ----
        {
            const int tx = lane;
            const int ci = (tx & 15) * 4;
            const int ha = tx >> 4;
            const int hb = 2 + (tx >> 4);
            #pragma unroll
            for (int i = 0; i < 4; i++) {
                int lrow = wid * 4 + i;
                int row  = row0 + lrow;
                if (row >= n) continue;

                float4 va = *(float4*)&Vs[lrow * VS + tx * 4];
                float4 vb = *(float4*)&Vs[lrow * VS + 128 + tx * 4];
                float vv[8];
                vv[0] = va.x + __ldg(&br[tx * 4 + 0]);
                vv[1] = va.y + __ldg(&br[tx * 4 + 1]);
                vv[2] = va.z + __ldg(&br[tx * 4 + 2]);
                vv[3] = va.w + __ldg(&br[tx * 4 + 3]);
                vv[4] = vb.x + __ldg(&br[128 + tx * 4 + 0]);
                vv[5] = vb.y + __ldg(&br[128 + tx * 4 + 1]);
                vv[6] = vb.z + __ldg(&br[128 + tx * 4 + 2]);
                vv[7] = vb.w + __ldg(&br[128 + tx * 4 + 3]);

                float pqa = 0.f, pka = 0.f, pqb2 = 0.f, pkb2 = 0.f;
                #pragma unroll
                for (int j = 0; j < 4; j++) {
                    pqa  = fmaf(vv[j],     __ldg(&rel_q[ha * 64 + ci + j]), pqa);
                    pka  = fmaf(vv[j],     __ldg(&rel_k[ha * 64 + ci + j]), pka);
                    pqb2 = fmaf(vv[4 + j], __ldg(&rel_q[hb * 64 + ci + j]), pqb2);
                    pkb2 = fmaf(vv[4 + j], __ldg(&rel_k[hb * 64 + ci + j]), pkb2);
                }
                #pragma unroll
                for (int o = 8; o; o >>= 1) {
                    pqa  += __shfl_xor_sync(0xffffffffu, pqa, o);
                    pka  += __shfl_xor_sync(0xffffffffu, pka, o);
                    pqb2 += __shfl_xor_sync(0xffffffffu, pqb2, o);
                    pkb2 += __shfl_xor_sync(0xffffffffu, pkb2, o);
                }

                float n1 = 1.0f + (float)__ldcg(&g_mask[row])
                                + (float)__ldcg(&g_mask[N_PAD + row])
                                + (float)__ldcg(&g_mask[2 * N_PAD + row]);
                float wa = head_w(pqa, pka, n1);
                float wb2 = head_w(pqb2, pkb2, n1);

                float o8[8];
                float s1 = 0.f, s2 = 0.f;
                #pragma unroll
                for (int j = 0; j < 4; j++) {
                    o8[j]     = fmaxf(vv[j] * wa, 0.f);
                    o8[4 + j] = fmaxf(vv[4 + j] * wb2, 0.f);
                }
                #pragma unroll
                for (int j = 0; j < 8; j++) { s1 += o8[j]; s2 = fmaf(o8[j], o8[j], s2); }
                #pragma unroll
                for (int o = 16; o; o >>= 1) {
                    s1 += __shfl_xor_sync(0xffffffffu, s1, o);
                    s2 += __shfl_xor_sync(0xffffffffu, s2, o);
                }
                float mu  = s1 * (1.0f / 256.0f);
                float var = s2 * (1.0f / 256.0f) - mu * mu;
                float rs  = rsqrtf(var + LN_EPS);

                float4 w0, w1;
                w0.x = (o8[0] - mu) * rs * __ldg(&ln_g[tx * 4 + 0]) + __ldg(&ln_b[tx * 4 + 0]);
                w0.y = (o8[1] - mu) * rs * __ldg(&ln_g[tx * 4 + 1]) + __ldg(&ln_b[tx * 4 + 1]);
                w0.z = (o8[2] - mu) * rs * __ldg(&ln_g[tx * 4 + 2]) + __ldg(&ln_b[tx * 4 + 2]);
                w0.w = (o8[3] - mu) * rs * __ldg(&ln_g[tx * 4 + 3]) + __ldg(&ln_b[tx * 4 + 3]);
                w1.x = (o8[4] - mu) * rs * __ldg(&ln_g[128 + tx * 4 + 0]) + __ldg(&ln_b[128 + tx * 4 + 0]);
                w1.y = (o8[5] - mu) * rs * __ldg(&ln_g[128 + tx * 4 + 1]) + __ldg(&ln_b[128 + tx * 4 + 1]);
                w1.z = (o8[6] - mu) * rs * __ldg(&ln_g[128 + tx * 4 + 2]) + __ldg(&ln_b[128 + tx * 4 + 2]);
                w1.w = (o8[7] - mu) * rs * __ldg(&ln_g[128 + tx * 4 + 3]) + __ldg(&ln_b[128 + tx * 4 + 3]);
                *(float4*)&out[(size_t)row * DIM + tx * 4]       = w0;
                *(float4*)&out[(size_t)row * DIM + 128 + tx * 4] = w1;
            }
        }

        // ---- stage A(next) to A16 (all warps past B2 => all LDSMs done) ----
        if (snext < ntiles) {
            #pragma unroll
            for (int j = 0; j < 4; j++) {
                uint4 h = make_uint4(pack_f16(vA[2*j].x,   vA[2*j].y),
                                     pack_f16(vA[2*j].z,   vA[2*j].w),
                                     pack_f16(vA[2*j+1].x, vA[2*j+1].y),
                                     pack_f16(vA[2*j+1].z, vA[2*j+1].w));
                *(uint4*)(aplane + swz(abase + j * 16)) = h;
            }
        }
    }
}

// ---------------- launcher: ONE kernel ----------------
extern "C" void kernel_launch(void* const* d_in, const int* in_sizes, int n_in,
                              void* d_out, int out_size)
{
    const float* feat  = (const float*)d_in[0];
    const float* Wr    = (const float*)d_in[3];
    const float* br    = (const float*)d_in[4];
    const float* rel_q = (const float*)d_in[7];
    const float* rel_k = (const float*)d_in[8];
    const float* ln_g  = (const float*)d_in[9];
    const float* ln_b  = (const float*)d_in[10];
    const int*   dst0  = (const int*)d_in[12];
    const int*   dst1  = (const int*)d_in[14];
    const int*   dst2  = (const int*)d_in[16];

    int n  = in_sizes[0] / DIM;   // 50000
    int E  = in_sizes[12];        // 400000
    int E4 = E / 4;

    static bool attr_set = false;
    if (!attr_set) {
        cudaFuncSetAttribute(fused_kernel,
                             cudaFuncAttributeMaxDynamicSharedMemorySize, SMEM_BYTES);
        cudaFuncSetAttribute(fused_kernel,
                             cudaFuncAttributePreferredSharedMemoryCarveout, 100);
        attr_set = true;
    }

    fused_kernel<<<NCTA, THREADS, SMEM_BYTES>>>(
        feat, Wr, br, rel_q, rel_k, ln_g, ln_b,
        dst0, dst1, dst2, (float*)d_out, n, E4);
}

// round 17
// speedup vs baseline: 1.6638x; 1.6638x over previous
#include <cuda_runtime.h>
#include <cuda_fp16.h>
#include <cstdint>

#define N_PAD   50048
#define DIM     256
#define NEG     0.2f
#define LN_EPS  1e-5f
#define THREADS 512

// SMEM layout (bytes): B 4 chunk-planes (256 rows x 128B each) | A16 4 planes | Vs
#define B_OFF    0
#define B_CHUNK  32768
#define A16_OFF  131072
#define VS_OFF   163840
#define VS       264
#define SMEM_BYTES (VS_OFF + 64 * VS * 4)   // 231424

// ---------------- scratch ----------------
__device__ unsigned char g_mask[3 * N_PAD];
// Wr fp16, chunk-major packed pairs: g_wh[(c*256+n)*32 + k2]
__device__ uint32_t g_wh[4 * 256 * 32];

// ---------------- helpers ----------------
__device__ __forceinline__ uint32_t pack_f16(float a, float b) {
    __half2 h = __floats2half2_rn(a, b);
    return *reinterpret_cast<uint32_t*>(&h);
}
__device__ __forceinline__ uint32_t s2u(const void* p) {
    return (uint32_t)__cvta_generic_to_shared(p);
}
__device__ __forceinline__ uint32_t swz(uint32_t off) {   // SW128
    return off ^ ((off >> 3) & 0x70);
}
__device__ __forceinline__ void cpasync16(uint32_t dst, const void* src) {
    asm volatile("cp.async.cg.shared.global [%0], [%1], 16;" :: "r"(dst), "l"(src));
}
__device__ __forceinline__ void cpcommit() { asm volatile("cp.async.commit_group;"); }
__device__ __forceinline__ void cpwait0()  { asm volatile("cp.async.wait_group 0;"); }
__device__ __forceinline__ void ldmx4(uint32_t r[4], uint32_t addr) {
    asm volatile("ldmatrix.sync.aligned.m8n8.x4.shared.b16 {%0,%1,%2,%3}, [%4];"
                 : "=r"(r[0]), "=r"(r[1]), "=r"(r[2]), "=r"(r[3]) : "r"(addr));
}
__device__ __forceinline__ void mma16816(float c[4], const uint32_t a[4],
                                         uint32_t b0, uint32_t b1) {
    asm("mma.sync.aligned.m16n8k16.row.col.f32.f16.f16.f32 "
        "{%0,%1,%2,%3}, {%4,%5,%6,%7}, {%8,%9}, {%0,%1,%2,%3};"
        : "+f"(c[0]), "+f"(c[1]), "+f"(c[2]), "+f"(c[3])
        : "r"(a[0]), "r"(a[1]), "r"(a[2]), "r"(a[3]), "r"(b0), "r"(b1));
}
__device__ __forceinline__ float head_w(float q, float kv, float n1) {
    float x1 = q + kv;
    float z1 = fmaxf(x1, NEG * x1);
    float z0 = fmaxf(q,  NEG * q);
    float m  = fmaxf(z1, z0);
    float e1 = expf(z1 - m);
    float e0 = expf(z0 - m);
    float f1 = n1 * e1;
    return f1 / (f1 + (4.0f - n1) * e0);
}

// ---------------- prep: Wr -> fp16 + edge scatter (validated R7/R8) ----------------
#define W_BLOCKS 16
__global__ void prep_kernel(const float* __restrict__ Wr,
                            const int* __restrict__ d0,
                            const int* __restrict__ d1,
                            const int* __restrict__ d2, int E4)
{
    int b = blockIdx.x;
    if (b < W_BLOCKS) {
        int t   = b * 256 + threadIdx.x;   // < 4096
        int nc  = t >> 4;
        int seg = t & 15;
        int kb  = seg * 16;
        uint32_t h[8];
        #pragma unroll
        for (int p = 0; p < 8; p++) {
            float x0 = Wr[(size_t)(kb + 2 * p)     * 256 + nc];
            float x1 = Wr[(size_t)(kb + 2 * p + 1) * 256 + nc];
            h[p] = pack_f16(x0, x1);
        }
        int c = seg >> 2;
        size_t base = ((size_t)(c * 256 + nc)) * 32 + (seg & 3) * 8;
        *(uint4*)&g_wh[base]     = make_uint4(h[0], h[1], h[2], h[3]);
        *(uint4*)&g_wh[base + 4] = make_uint4(h[4], h[5], h[6], h[7]);
        return;
    }
    b -= W_BLOCKS;
    int i = b * 256 + threadIdx.x;
    if (i >= E4) return;
    int4 a  = ((const int4*)d0)[i];
    int4 bb = ((const int4*)d1)[i];
    int4 cc = ((const int4*)d2)[i];
    if (!g_mask[a.x]) g_mask[a.x] = 1;
    if (!g_mask[a.y]) g_mask[a.y] = 1;
    if (!g_mask[a.z]) g_mask[a.z] = 1;
    if (!g_mask[a.w]) g_mask[a.w] = 1;
    if (!g_mask[N_PAD + bb.x]) g_mask[N_PAD + bb.x] = 1;
    if (!g_mask[N_PAD + bb.y]) g_mask[N_PAD + bb.y] = 1;
    if (!g_mask[N_PAD + bb.z]) g_mask[N_PAD + bb.z] = 1;
    if (!g_mask[N_PAD + bb.w]) g_mask[N_PAD + bb.w] = 1;
    if (!g_mask[2 * N_PAD + cc.x]) g_mask[2 * N_PAD + cc.x] = 1;
    if (!g_mask[2 * N_PAD + cc.y]) g_mask[2 * N_PAD + cc.y] = 1;
    if (!g_mask[2 * N_PAD + cc.z]) g_mask[2 * N_PAD + cc.z] = 1;
    if (!g_mask[2 * N_PAD + cc.w]) g_mask[2 * N_PAD + cc.w] = 1;
}

// ---------------- persistent GEMM: B resident, grid-stride (R13 + coalesced A) ---
// 512 threads = 16 warps, warp grid 2m x 8n, warp tile 32x32 (validated).
__global__ __launch_bounds__(THREADS, 1)
void gemm_epilogue(const float* __restrict__ feat,
                   const float* __restrict__ br,
                   const float* __restrict__ rel_q,
                   const float* __restrict__ rel_k,
                   const float* __restrict__ ln_g,
                   const float* __restrict__ ln_b,
                   float* __restrict__ out, int n)
{
    extern __shared__ char smem[];
    const uint32_t su = s2u(smem);
    const int tid  = threadIdx.x;
    const int wid  = tid >> 5;
    const int lane = tid & 31;
    const int wm   = wid & 1;      // rows wm*32..+31
    const int wn   = wid >> 1;     // cols wn*32..+31

    // ---- load ALL of B once (4 chunks, 128 KB) ----
    {
        const int bn = tid >> 1;
        const int bj = (tid & 1) * 4;
        #pragma unroll
        for (int c = 0; c < 4; c++) {
            const uint32_t* bf = g_wh + (size_t)c * 8192 + (size_t)bn * 32 + bj * 4;
            const uint32_t dstb = su + B_OFF + (uint32_t)c * B_CHUNK;
            #pragma unroll
            for (int u = 0; u < 4; u++)
                cpasync16(dstb + swz((uint32_t)(bn * 128 + (bj + u) * 16)), bf + u * 4);
        }
        cpcommit();
    }

    // loop-invariant epilogue constants (validated R12/R13)
    const int tx = lane;
    const int ci = (tx & 15) * 4;
    const int ha = tx >> 4;
    const int hb = 2 + (tx >> 4);
    float rqa[4], rka[4], rqb[4], rkb[4];
    float bra[4], brb[4], ga[4], gb[4], ba[4], bb[4];
    #pragma unroll
    for (int j = 0; j < 4; j++) {
        rqa[j] = rel_q[ha * 64 + ci + j];
        rka[j] = rel_k[ha * 64 + ci + j];
        rqb[j] = rel_q[hb * 64 + ci + j];
        rkb[j] = rel_k[hb * 64 + ci + j];
        int colA = tx * 4 + j;
        int colB = 128 + tx * 4 + j;
        bra[j] = br[colA];   brb[j] = br[colB];
        ga[j]  = ln_g[colA]; gb[j]  = ln_g[colB];
        ba[j]  = ln_b[colA]; bb[j]  = ln_b[colB];
    }

    // fragment address components (validated)
    const int l7  = lane & 7;
    const int q01 = (lane >> 3) & 1;
    const int q23 = lane >> 4;
    uint32_t arowb[2];
    #pragma unroll
    for (int mt = 0; mt < 2; mt++)
        arowb[mt] = (uint32_t)((wm * 32 + mt * 16 + q01 * 8 + l7) * 128);
    const uint32_t bg   = (uint32_t)((lane >> 3) * 16);
    const uint32_t brb0 = (uint32_t)((wn * 32 + l7) * 128);

    // ---- A staging mapping: COALESCED (lanes 0..7 contiguous within a row) ----
    // thread (arow = tid>>3, aq = tid&7); v[i] = feat_row[i*8 + aq] (float4)
    // float4 i covers k = i*32 + aq*4 .. +3 -> chunk i>>1, byte row*128+(i&1)*64+aq*8
    const int arow = tid >> 3;
    const int aq   = tid & 7;
    char* planebase = smem + A16_OFF;
    const uint32_t arow128 = (uint32_t)(arow * 128);

    float* Vs = (float*)(smem + VS_OFF);

    cpwait0();
    __syncthreads();     // B resident

    const int ntiles = (n + 63) >> 6;   // 782
    for (int s = blockIdx.x; s < ntiles; s += gridDim.x) {
        const int row0 = s * 64;

        // ---- A: coalesced load 64x256 fp32, convert -> A16 planes ----
        {
            int gr = row0 + arow; if (gr >= n) gr = n - 1;
            const float4* af = (const float4*)(feat + (size_t)gr * 256) + aq;
            float4 v[8];
            #pragma unroll
            for (int i = 0; i < 8; i++) v[i] = af[i * 8];
            #pragma unroll
            for (int i = 0; i < 8; i++) {
                uint2 h;
                h.x = pack_f16(v[i].x, v[i].y);
                h.y = pack_f16(v[i].z, v[i].w);
                uint32_t off = arow128 + (uint32_t)((i & 1) * 64 + aq * 8);
                *(uint2*)(planebase + (i >> 1) * 8192 + swz(off)) = h;
            }
        }
        __syncthreads();   // A16 ready (also: prev epilogue Vs reads done)

        float acc[2][4][4];
        #pragma unroll
        for (int mt = 0; mt < 2; mt++)
            #pragma unroll
            for (int nt = 0; nt < 4; nt++)
                #pragma unroll
                for (int q = 0; q < 4; q++) acc[mt][nt][q] = 0.0f;

        // ---- compute: 4 chunks, all operands SMEM-resident (validated R13) ----
        #pragma unroll
        for (int c = 0; c < 4; c++) {
            const uint32_t sa = su + A16_OFF + (uint32_t)c * 8192;
            const uint32_t sb = su + B_OFF + (uint32_t)c * B_CHUNK;
            #pragma unroll
            for (int p = 0; p < 2; p++) {
                uint32_t bh[4][4];
                #pragma unroll
                for (int nt = 0; nt < 4; nt++)
                    ldmx4(bh[nt], sb + swz(brb0 + (uint32_t)(nt * 1024 + p * 64) + bg));
                #pragma unroll
                for (int kk = 0; kk < 2; kk++) {
                    uint32_t ah[2][4];
                    #pragma unroll
                    for (int mt = 0; mt < 2; mt++)
                        ldmx4(ah[mt], sa + swz(arowb[mt] + (uint32_t)((p * 2 + kk) * 32 + q23 * 16)));
                    mma16816(acc[0][0], ah[0], bh[0][2*kk], bh[0][2*kk+1]);
                    mma16816(acc[1][0], ah[1], bh[0][2*kk], bh[0][2*kk+1]);
                    mma16816(acc[0][1], ah[0], bh[1][2*kk], bh[1][2*kk+1]);
                    mma16816(acc[1][1], ah[1], bh[1][2*kk], bh[1][2*kk+1]);
                    mma16816(acc[0][2], ah[0], bh[2][2*kk], bh[2][2*kk+1]);
                    mma16816(acc[1][2], ah[1], bh[2][2*kk], bh[2][2*kk+1]);
                    mma16816(acc[0][3], ah[0], bh[3][2*kk], bh[3][2*kk+1]);
                    mma16816(acc[1][3], ah[1], bh[3][2*kk], bh[3][2*kk+1]);
                }
            }
        }

        // ---- stage v tile to dedicated Vs ----
        {
            const int rg = lane >> 2;
            const int cq = (lane & 3) * 2;
            #pragma unroll
            for (int mt = 0; mt < 2; mt++)
                #pragma unroll
                for (int nt = 0; nt < 4; nt++) {
                    int r  = wm * 32 + mt * 16 + rg;
                    int cc = wn * 32 + nt * 8 + cq;
                    Vs[r * VS + cc]           = acc[mt][nt][0];
                    Vs[r * VS + cc + 1]       = acc[mt][nt][1];
                    Vs[(r + 8) * VS + cc]     = acc[mt][nt][2];
                    Vs[(r + 8) * VS + cc + 1] = acc[mt][nt][3];
                }
        }
        __syncthreads();   // Vs complete (also: all LDSM of A16 done)

        // ---- epilogue (validated): 16 warps x 4 rows ----
        #pragma unroll
        for (int i = 0; i < 4; i++) {
            int lrow = wid * 4 + i;
            int row  = row0 + lrow;
            if (row >= n) continue;

            float4 va = *(float4*)&Vs[lrow * VS + tx * 4];
            float4 vb = *(float4*)&Vs[lrow * VS + 128 + tx * 4];
            float vv[8];
            vv[0] = va.x + bra[0]; vv[1] = va.y + bra[1];
            vv[2] = va.z + bra[2]; vv[3] = va.w + bra[3];
            vv[4] = vb.x + brb[0]; vv[5] = vb.y + brb[1];
            vv[6] = vb.z + brb[2]; vv[7] = vb.w + brb[3];

            float pqa = 0.f, pka = 0.f, pqb = 0.f, pkb = 0.f;
            #pragma unroll
            for (int j = 0; j < 4; j++) {
                pqa = fmaf(vv[j],     rqa[j], pqa);
                pka = fmaf(vv[j],     rka[j], pka);
                pqb = fmaf(vv[4 + j], rqb[j], pqb);
                pkb = fmaf(vv[4 + j], rkb[j], pkb);
            }
            #pragma unroll
            for (int o = 8; o; o >>= 1) {
                pqa += __shfl_xor_sync(0xffffffffu, pqa, o);
                pka += __shfl_xor_sync(0xffffffffu, pka, o);
                pqb += __shfl_xor_sync(0xffffffffu, pqb, o);
                pkb += __shfl_xor_sync(0xffffffffu, pkb, o);
            }

            float n1 = 1.0f + (float)g_mask[row] + (float)g_mask[N_PAD + row]
                            + (float)g_mask[2 * N_PAD + row];
            float wa = head_w(pqa, pka, n1);
            float wb = head_w(pqb, pkb, n1);

            float o8[8];
            float s1 = 0.f, s2 = 0.f;
            #pragma unroll
            for (int j = 0; j < 4; j++) {
                o8[j]     = fmaxf(vv[j] * wa, 0.f);
                o8[4 + j] = fmaxf(vv[4 + j] * wb, 0.f);
            }
            #pragma unroll
            for (int j = 0; j < 8; j++) { s1 += o8[j]; s2 = fmaf(o8[j], o8[j], s2); }
            #pragma unroll
            for (int o = 16; o; o >>= 1) {
                s1 += __shfl_xor_sync(0xffffffffu, s1, o);
                s2 += __shfl_xor_sync(0xffffffffu, s2, o);
            }
            float mu  = s1 * (1.0f / 256.0f);
            float var = s2 * (1.0f / 256.0f) - mu * mu;
            float rs  = rsqrtf(var + LN_EPS);

            float4 w0, w1;
            w0.x = (o8[0] - mu) * rs * ga[0] + ba[0];
            w0.y = (o8[1] - mu) * rs * ga[1] + ba[1];
            w0.z = (o8[2] - mu) * rs * ga[2] + ba[2];
            w0.w = (o8[3] - mu) * rs * ga[3] + ba[3];
            w1.x = (o8[4] - mu) * rs * gb[0] + bb[0];
            w1.y = (o8[5] - mu) * rs * gb[1] + bb[1];
            w1.z = (o8[6] - mu) * rs * gb[2] + bb[2];
            w1.w = (o8[7] - mu) * rs * gb[3] + bb[3];
            *(float4*)&out[(size_t)row * DIM + tx * 4]       = w0;
            *(float4*)&out[(size_t)row * DIM + 128 + tx * 4] = w1;
        }
    }
}

// ---------------- launcher ----------------
extern "C" void kernel_launch(void* const* d_in, const int* in_sizes, int n_in,
                              void* d_out, int out_size)
{
    const float* feat  = (const float*)d_in[0];
    const float* Wr    = (const float*)d_in[3];
    const float* br    = (const float*)d_in[4];
    const float* rel_q = (const float*)d_in[7];
    const float* rel_k = (const float*)d_in[8];
    const float* ln_g  = (const float*)d_in[9];
    const float* ln_b  = (const float*)d_in[10];
    const int*   dst0  = (const int*)d_in[12];
    const int*   dst1  = (const int*)d_in[14];
    const int*   dst2  = (const int*)d_in[16];

    int n  = in_sizes[0] / DIM;   // 50000
    int E  = in_sizes[12];        // 400000
    int E4 = E / 4;

    static bool attr_set = false;
    if (!attr_set) {
        cudaFuncSetAttribute(gemm_epilogue,
                             cudaFuncAttributeMaxDynamicSharedMemorySize, SMEM_BYTES);
        cudaFuncSetAttribute(gemm_epilogue,
                             cudaFuncAttributePreferredSharedMemoryCarveout, 100);
        attr_set = true;
    }

    int scatter_blocks = (E4 + 255) / 256;
    prep_kernel<<<W_BLOCKS + scatter_blocks, 256>>>(Wr, dst0, dst1, dst2, E4);

    gemm_epilogue<<<148, THREADS, SMEM_BYTES>>>(
        feat, br, rel_q, rel_k, ln_g, ln_b, (float*)d_out, n);
}